// round 17
// baseline (speedup 1.0000x reference)
#include <cuda_runtime.h>
#include <math.h>
#include <stdint.h>

#define BB 64
#define TT 2048
#define DENC 512
#define DRNN 1024
#define DATT 128
#define NFQ 32
#define KW 31
#define PADW 15
#define NSUB 4              // subtiles per block (64 t each)
#define SMX2 32             // stats/partial granularity per row (64-t units)

typedef unsigned long long ull;

__device__ float g_pq[BB * DATT];
__device__ float g_part[BB * SMX2 * DENC];         // unnormalized ctx partials
__device__ __align__(16) float g_dfa[NFQ * DATT];  // densew transposed to [f][a]
__device__ float g_smax[BB * SMX2];
__device__ float g_ssum[BB * SMX2];

__device__ __forceinline__ float tanh_fast(float x) {
    float y;
    asm("tanh.approx.f32 %0, %1;" : "=f"(y) : "f"(x));
    return y;
}
__device__ __forceinline__ void unpack2(ull v, float& lo, float& hi) {
    asm("mov.b64 {%0, %1}, %2;" : "=f"(lo), "=f"(hi) : "l"(v));
}
__device__ __forceinline__ ull pack2(float lo, float hi) {
    ull r;
    asm("mov.b64 %0, {%1, %2};" : "=l"(r) : "f"(lo), "f"(hi));
    return r;
}
__device__ __forceinline__ ull fma2(ull a, ull b, ull c) {
    ull d;
    asm("fma.rn.f32x2 %0, %1, %2, %3;" : "=l"(d) : "l"(a), "l"(b), "l"(c));
    return d;
}
__device__ __forceinline__ ull add2(ull a, ull b) {
    ull d;
    asm("add.rn.f32x2 %0, %1, %2;" : "=l"(d) : "l"(a), "l"(b));
    return d;
}
#define BAR_COMPUTE() asm volatile("bar.sync 1, 256;" ::: "memory")
#define BAR_STREAM()  asm volatile("bar.sync 2, 256;" ::: "memory")

// ---------------------------------------------------------------------------
// Prep: transpose densew [a][f] -> g_dfa [f][a]
// ---------------------------------------------------------------------------
__global__ __launch_bounds__(256) void prep_dense(const float* __restrict__ densew) {
    const int i = blockIdx.x * 256 + threadIdx.x;
    const int f = i >> 7, a = i & 127;
    g_dfa[i] = densew[a * NFQ + f];
}

// ---------------------------------------------------------------------------
// Kernel A: pq[b,a] = sum_d ahs[b,d] * qw[a,d]   grid (B, 16), 8 a's per block
// ---------------------------------------------------------------------------
__global__ __launch_bounds__(128) void pq_kernel(const float* __restrict__ ahs,
                                                 const float* __restrict__ qw) {
    const int b = blockIdx.x;
    const int abase = blockIdx.y * 8;
    __shared__ __align__(16) float ahs_s[DRNN];
    for (int i = threadIdx.x; i < DRNN / 4; i += 128)
        reinterpret_cast<float4*>(ahs_s)[i] =
            reinterpret_cast<const float4*>(ahs + (size_t)b * DRNN)[i];
    __syncthreads();
    const int w = threadIdx.x >> 5, lane = threadIdx.x & 31;
    #pragma unroll
    for (int aa = 0; aa < 2; aa++) {
        const int a = abase + w * 2 + aa;
        const float4* qr = reinterpret_cast<const float4*>(qw + (size_t)a * DRNN);
        float acc = 0.f;
        #pragma unroll
        for (int d4 = lane; d4 < DRNN / 4; d4 += 32) {
            const float4 q = qr[d4];
            const float4 h = reinterpret_cast<const float4*>(ahs_s)[d4];
            acc += q.x * h.x + q.y * h.y + q.z * h.z + q.w * h.w;
        }
        #pragma unroll
        for (int off = 16; off; off >>= 1) acc += __shfl_xor_sync(0xffffffffu, acc, off);
        if (lane == 0) g_pq[b * DATT + a] = acc;
    }
}

// ---------------------------------------------------------------------------
// Kernel B (pipelined mega): 256-t block tile, 4 subtiles of 64 t.
// Warps 0-7 = compute group (conv+dense+tanh+dot+partial softmax).
// Warps 8-15 = stream group (ctx accumulation of previous subtile).
// Stages: c0 | c1||s0 | c2||s1 | c3||s2 | s3, __syncthreads between stages.
// ---------------------------------------------------------------------------
__global__ __launch_bounds__(512, 2) void align_kernel(
    const float* __restrict__ pm,      // [B,T,128]
    const float* __restrict__ mem,     // [B,T,512]
    const float* __restrict__ awc,     // [B,2,T]
    const float* __restrict__ convw,   // [32,2,31]
    const float* __restrict__ vw,      // [128]
    const unsigned char* __restrict__ mask,  // [B,T]
    float* __restrict__ wts_out)       // [B,T] exp-shifted (unnormalized)
{
    const int b = blockIdx.y;
    const int t0 = blockIdx.x * 256;
    const int tid = threadIdx.x;
    const int group = tid >> 8;        // 0 = compute, 1 = stream
    const int ctid = tid & 255;

    __shared__ __align__(16) float pq_s[DATT];
    __shared__ __align__(16) float val_s[DATT];
    __shared__ __align__(16) float dense_s[NFQ * DATT];  // [f][a]
    __shared__ float convw_s[NFQ * 2 * KW];
    __shared__ float awc_s[2][286];                      // 256 + 2*15
    __shared__ __align__(16) float loc_s[NFQ * 64];      // [f][tt] per subtile
    __shared__ float part_s[2][4][32];                   // [thalf][aw][tt]
    __shared__ float redm_s[2];
    __shared__ float ew_s[2][64];                        // double-buffered
    __shared__ __align__(16) float4 sc_s[128];           // stream reduce scratch

    // ---- stage shared (all 512 threads) ----
    if (tid < DATT) { pq_s[tid] = g_pq[b * DATT + tid]; val_s[tid] = vw[tid]; }
    #pragma unroll
    for (int i = tid; i < NFQ * DATT / 4; i += 512)
        reinterpret_cast<float4*>(dense_s)[i] = reinterpret_cast<const float4*>(g_dfa)[i];
    for (int i = tid; i < NFQ * 2 * KW; i += 512) convw_s[i] = convw[i];
    // awc halo for full 256-t tile: positions t0-15 .. t0+270
    for (int i = tid; i < 2 * 286; i += 512) {
        const int c = i / 286, p = i - c * 286;
        const int pos = t0 - PADW + p;
        awc_s[c][p] = (pos >= 0 && pos < TT) ? awc[((size_t)b * 2 + c) * TT + pos] : 0.f;
    }
    __syncthreads();

    // ---- pipeline over 5 stages ----
    for (int st = 0; st < NSUB + 1; st++) {
        if (group == 0 && st < NSUB) {
            // ============ COMPUTE subtile st (threads 0-255) ============
            const int sub = st;
            const int ts0 = t0 + sub * 64;
            const int w = ctid >> 5, lane = ctid & 31;
            const int thalf = w >> 2, aw = w & 3;
            const int tg = lane >> 2, ag = lane & 3;
            const int abase = aw * 32 + ag * 8;
            const int tloc = thalf * 32 + tg * 4;

            // conv: f = ctid>>3, tt range [(ctid&7)*8, +8) within subtile
            {
                const int f = ctid >> 3;
                const int ttb = (ctid & 7) * 8;
                const int base = sub * 64 + ttb;
                const float* cw = convw_s + f * 62;
                float acc[8], w0r[8], w1r[8];
                #pragma unroll
                for (int j = 0; j < 8; j++) {
                    acc[j] = 0.f;
                    w0r[j] = awc_s[0][base + j];
                    w1r[j] = awc_s[1][base + j];
                }
                #pragma unroll
                for (int k = 0; k < KW; k++) {
                    const float wk0 = cw[k], wk1 = cw[KW + k];
                    #pragma unroll
                    for (int j = 0; j < 8; j++) {
                        const int r = (k + j) & 7;
                        acc[j] += w0r[r] * wk0 + w1r[r] * wk1;
                    }
                    if (k < KW - 1) {
                        w0r[k & 7] = awc_s[0][base + k + 8];
                        w1r[k & 7] = awc_s[1][base + k + 8];
                    }
                }
                #pragma unroll
                for (int j = 0; j < 8; j++) loc_s[f * 64 + ttb + j] = acc[j];
            }
            BAR_COMPUTE();

            // dense (packed f32x2): lane tile 4t x 8a
            ull acc2p[4][4];
            #pragma unroll
            for (int i = 0; i < 4; i++)
                #pragma unroll
                for (int jj = 0; jj < 4; jj++) acc2p[i][jj] = 0ull;
            #pragma unroll 4
            for (int f = 0; f < NFQ; f++) {
                const float4 lv = *reinterpret_cast<const float4*>(&loc_s[f * 64 + tloc]);
                const ulonglong2* dp =
                    reinterpret_cast<const ulonglong2*>(&dense_s[f * DATT + abase]);
                const ulonglong2 q0 = dp[0], q1 = dp[1];
                const ull dvp[4] = {q0.x, q0.y, q1.x, q1.y};
                ull lvp[4];
                lvp[0] = pack2(lv.x, lv.x);
                lvp[1] = pack2(lv.y, lv.y);
                lvp[2] = pack2(lv.z, lv.z);
                lvp[3] = pack2(lv.w, lv.w);
                #pragma unroll
                for (int i = 0; i < 4; i++)
                    #pragma unroll
                    for (int jj = 0; jj < 4; jj++)
                        acc2p[i][jj] = fma2(lvp[i], dvp[jj], acc2p[i][jj]);
            }

            const ulonglong2* pqp = reinterpret_cast<const ulonglong2*>(&pq_s[abase]);
            const ulonglong2 pqa = pqp[0], pqb = pqp[1];
            const ull pq2[4] = {pqa.x, pqa.y, pqb.x, pqb.y};
            float vr[8];
            #pragma unroll
            for (int j = 0; j < 8; j++) vr[j] = val_s[abase + j];

            // energies + partial value-dot
            #pragma unroll
            for (int i = 0; i < 4; i++) {
                const int t = ts0 + tloc + i;
                const ulonglong2* pmp = reinterpret_cast<const ulonglong2*>(
                    pm + ((size_t)b * TT + t) * DATT + abase);
                const ulonglong2 m0 = pmp[0], m1 = pmp[1];
                const ull pv[4] = {m0.x, m0.y, m1.x, m1.y};
                float s = 0.f;
                #pragma unroll
                for (int jj = 0; jj < 4; jj++) {
                    const ull e2 = add2(add2(pq2[jj], pv[jj]), acc2p[i][jj]);
                    float elo, ehi;
                    unpack2(e2, elo, ehi);
                    s += tanh_fast(elo) * vr[2 * jj] + tanh_fast(ehi) * vr[2 * jj + 1];
                }
                s += __shfl_xor_sync(0xffffffffu, s, 1);
                s += __shfl_xor_sync(0xffffffffu, s, 2);
                if (ag == 0) part_s[thalf][aw][tg * 4 + i] = s;
            }
            BAR_COMPUTE();

            // partial softmax over this subtile's 64 t's
            float sval = -INFINITY;
            if (ctid < 64) {
                const int th = ctid >> 5, tt = ctid & 31;
                sval = part_s[th][0][tt] + part_s[th][1][tt] +
                       part_s[th][2][tt] + part_s[th][3][tt];
                if (mask[(size_t)b * TT + ts0 + ctid]) sval = -INFINITY;
            }
            float m = sval;
            #pragma unroll
            for (int o = 16; o; o >>= 1) m = fmaxf(m, __shfl_xor_sync(0xffffffffu, m, o));
            if (ctid < 64 && lane == 0) redm_s[ctid >> 5] = m;
            BAR_COMPUTE();
            const float Mb = fmaxf(redm_s[0], redm_s[1]);
            if (ctid < 64) {
                const float e = (sval == -INFINITY) ? 0.f : __expf(sval - Mb);
                ew_s[sub & 1][ctid] = e;
                wts_out[(size_t)b * TT + ts0 + ctid] = e;
            }
            BAR_COMPUTE();
            if (ctid < 32) {
                float es = ew_s[sub & 1][ctid] + ew_s[sub & 1][ctid + 32];
                #pragma unroll
                for (int o = 16; o; o >>= 1) es += __shfl_xor_sync(0xffffffffu, es, o);
                if (ctid == 0) {
                    g_smax[b * SMX2 + blockIdx.x * NSUB + sub] = Mb;
                    g_ssum[b * SMX2 + blockIdx.x * NSUB + sub] = es;
                }
            }
        } else if (group == 1 && st >= 1) {
            // ============ STREAM subtile st-1 (threads 256-511) ============
            const int sub = st - 1;
            const int ts0 = t0 + sub * 64;
            const int d4 = ctid & 127;
            const int trow = ctid >> 7;
            const float* ew = ew_s[sub & 1];
            const float4* mrow = reinterpret_cast<const float4*>(
                mem + ((size_t)b * TT + ts0) * DENC) + d4;
            float4 cacc = make_float4(0.f, 0.f, 0.f, 0.f);
            #pragma unroll 16
            for (int i = trow; i < 64; i += 2) {
                const float ev = ew[i];
                const float4 mv = mrow[(size_t)i * (DENC / 4)];
                cacc.x += ev * mv.x;
                cacc.y += ev * mv.y;
                cacc.z += ev * mv.z;
                cacc.w += ev * mv.w;
            }
            if (trow == 1) sc_s[d4] = cacc;
            BAR_STREAM();
            if (trow == 0) {
                const float4 p = sc_s[d4];
                cacc.x += p.x; cacc.y += p.y; cacc.z += p.z; cacc.w += p.w;
                reinterpret_cast<float4*>(
                    g_part + ((size_t)b * SMX2 + blockIdx.x * NSUB + sub) * DENC)[d4] = cacc;
            }
        }
        __syncthreads();   // stage boundary: publishes ew_s / recycles buffers
    }
}

// ---------------------------------------------------------------------------
// Kernel E: stats combine + scaled reduce -> context; normalize weights
// grid (4, B), 128 threads; 32 partials per row.
// ---------------------------------------------------------------------------
__global__ __launch_bounds__(128) void ctx_reduce(float* __restrict__ ctx,
                                                  float* __restrict__ wts) {
    const int q = blockIdx.x, b = blockIdx.y;
    const int tid = threadIdx.x;
    const int lane = tid & 31, w = tid >> 5;
    __shared__ float scale_s[SMX2];
    __shared__ __align__(16) float4 sc_s[3 * 32];

    if (tid < 32) {
        const float mi = g_smax[b * SMX2 + lane];
        const float si = g_ssum[b * SMX2 + lane];
        float M = mi;
        #pragma unroll
        for (int o = 16; o; o >>= 1) M = fmaxf(M, __shfl_xor_sync(0xffffffffu, M, o));
        float p = (mi == -INFINITY) ? 0.f : si * __expf(mi - M);
        #pragma unroll
        for (int o = 16; o; o >>= 1) p += __shfl_xor_sync(0xffffffffu, p, o);
        scale_s[lane] = (mi == -INFINITY) ? 0.f : __expf(mi - M) / p;
    }
    __syncthreads();

    const int d4 = q * 32 + lane;
    float4 acc = make_float4(0.f, 0.f, 0.f, 0.f);
    #pragma unroll
    for (int j = 0; j < 8; j++) {
        const int s = w * 8 + j;
        const float sc = scale_s[s];
        const float4 p = reinterpret_cast<const float4*>(
            g_part + ((size_t)b * SMX2 + s) * DENC)[d4];
        acc.x += sc * p.x; acc.y += sc * p.y; acc.z += sc * p.z; acc.w += sc * p.w;
    }
    if (w > 0) sc_s[(w - 1) * 32 + lane] = acc;
    __syncthreads();
    if (w == 0) {
        #pragma unroll
        for (int r = 0; r < 3; r++) {
            const float4 p = sc_s[r * 32 + lane];
            acc.x += p.x; acc.y += p.y; acc.z += p.z; acc.w += p.w;
        }
        reinterpret_cast<float4*>(ctx + (size_t)b * DENC)[d4] = acc;
    }

    // normalize attention weights: block q covers t in [q*512, q*512+512)
    #pragma unroll
    for (int i = 0; i < 4; i++) {
        const int t = q * 512 + i * 128 + tid;
        wts[(size_t)b * TT + t] *= scale_s[t >> 6];
    }
}

// ---------------------------------------------------------------------------
// Entry
// ---------------------------------------------------------------------------
extern "C" void kernel_launch(void* const* d_in, const int* in_sizes, int n_in,
                              void* d_out, int out_size) {
    const float* ahs    = (const float*)d_in[0];
    const float* mem    = (const float*)d_in[1];
    const float* pm     = (const float*)d_in[2];
    const float* awc    = (const float*)d_in[3];
    const unsigned char* mask = (const unsigned char*)d_in[4];
    const float* qw     = (const float*)d_in[5];
    const float* vw     = (const float*)d_in[6];
    const float* convw  = (const float*)d_in[7];
    const float* densew = (const float*)d_in[8];

    float* out = (float*)d_out;
    float* ctx = out;               // [B, D_ENC]
    float* wts = out + BB * DENC;   // [B, T]

    prep_dense<<<NFQ * DATT / 256, 256>>>(densew);
    pq_kernel<<<dim3(BB, 16), 128>>>(ahs, qw);
    align_kernel<<<dim3(TT / 256, BB), 512>>>(pm, mem, awc, convw, vw, mask, wts);
    ctx_reduce<<<dim3(4, BB), 128>>>(ctx, wts);
}